// round 13
// baseline (speedup 1.0000x reference)
#include <cuda_runtime.h>
#include <cuda_fp16.h>
#include <math.h>

#define Bsz   2
#define Ls    2048
#define Cdim  1024
#define NH    16
#define HD    64
#define HARM  32
#define TOK   (Bsz*Ls)   // 4096

// ---------------- device scratch ----------------------------------------------------
__device__ float  g_w[4][HARM*Cdim];     // w transposed: [h][o]
__device__ float  g_R[TOK*96];           // qkv resonances
__device__ __half g_q[TOK*Cdim];         // Q fp16, pre-scaled by scale*log2e, d-pair-permuted
__device__ __half g_k[TOK*Cdim];         // K fp16, d-pair-permuted
__device__ __half g_v[Bsz*NH*HD*Ls];     // V fp16, transposed [bh][d][L], L-pair-permuted
__device__ float  g_att[TOK*Cdim];       // attention output [B,L,C] fp32
__device__ float  g_Ro[TOK*HARM];        // output-projection resonance

#define QSCALE (0.125f * 1.44269504088896340736f)   // headdim^-0.5 * log2(e)

__device__ __forceinline__ float ex2f(float x) {
    float r; asm("ex2.approx.f32 %0, %1;" : "=f"(r) : "f"(x)); return r;
}
__device__ __forceinline__ unsigned h2pk(float lo, float hi) {
    unsigned r; asm("cvt.rn.f16x2.f32 %0, %1, %2;" : "=r"(r) : "f"(hi), "f"(lo)); return r;
}
__device__ __forceinline__ void mma_f16(float d[4], const unsigned a[4],
                                        unsigned b0, unsigned b1) {
    asm("mma.sync.aligned.m16n8k16.row.col.f32.f16.f16.f32 "
        "{%0,%1,%2,%3}, {%4,%5,%6,%7}, {%8,%9}, {%0,%1,%2,%3};"
        : "+f"(d[0]), "+f"(d[1]), "+f"(d[2]), "+f"(d[3])
        : "r"(a[0]), "r"(a[1]), "r"(a[2]), "r"(a[3]), "r"(b0), "r"(b1));
}
__device__ __forceinline__ void cp16(float* dst, const void* src) {
    unsigned d = (unsigned)__cvta_generic_to_shared(dst);
    asm volatile("cp.async.cg.shared.global [%0], [%1], 16;" :: "r"(d), "l"(src));
}

// ---------------- kernel 1: w = amp * cos(phase), stored transposed [h][o] ----------
__global__ void k_w(const float* __restrict__ pq, const float* __restrict__ aq,
                    const float* __restrict__ pk, const float* __restrict__ ak,
                    const float* __restrict__ pv, const float* __restrict__ av,
                    const float* __restrict__ po, const float* __restrict__ ao) {
    int i = blockIdx.x * blockDim.x + threadIdx.x;
    int o = i >> 5, h = i & 31;
    int j = h * Cdim + o;
    g_w[0][j] = aq[i] * cosf(pq[i]);
    g_w[1][j] = ak[i] * cosf(pk[i]);
    g_w[2][j] = av[i] * cosf(pv[i]);
    g_w[3][j] = ao[i] * cosf(po[i]);
}

// ---------------- kernel 2: R = x @ [bq;bk;bv]^T  (bases are already [h][dim]) ------
// 16 tokens/block, 384 threads = 96 j-cols x 4 token-groups. float4 basis loads.
__global__ void __launch_bounds__(384) k_res96(const float* __restrict__ x,
                                               const float* __restrict__ bq,
                                               const float* __restrict__ bk,
                                               const float* __restrict__ bv) {
    extern __shared__ float xs[];     // [16][1024]
    int t0 = blockIdx.x * 16;
    const float4* xg = (const float4*)(x + (size_t)t0 * Cdim);
    float4* s4 = (float4*)xs;
    for (int i = threadIdx.x; i < 4096; i += 384) s4[i] = xg[i];
    __syncthreads();
    int j  = threadIdx.x % 96;
    int tg = threadIdx.x / 96;        // 0..3, four tokens each
    const float* br = (j < 32) ? (bq + (size_t)j*Cdim)
                   : (j < 64) ? (bk + (size_t)(j-32)*Cdim)
                              : (bv + (size_t)(j-64)*Cdim);
    const float4* b4 = (const float4*)br;
    const float4* x0 = (const float4*)(xs + (tg*4 + 0)*1024);
    const float4* x1 = (const float4*)(xs + (tg*4 + 1)*1024);
    const float4* x2 = (const float4*)(xs + (tg*4 + 2)*1024);
    const float4* x3 = (const float4*)(xs + (tg*4 + 3)*1024);
    float a0 = 0.f, a1 = 0.f, a2 = 0.f, a3 = 0.f;
    #pragma unroll 4
    for (int iq = 0; iq < 256; iq++) {
        float4 b = b4[iq];
        float4 v0 = x0[iq], v1 = x1[iq], v2 = x2[iq], v3 = x3[iq];
        a0 += b.x*v0.x + b.y*v0.y + b.z*v0.z + b.w*v0.w;
        a1 += b.x*v1.x + b.y*v1.y + b.z*v1.z + b.w*v1.w;
        a2 += b.x*v2.x + b.y*v2.y + b.z*v2.z + b.w*v2.w;
        a3 += b.x*v3.x + b.y*v3.y + b.z*v3.z + b.w*v3.w;
    }
    g_R[(size_t)(t0 + tg*4    )*96 + j] = a0;
    g_R[(size_t)(t0 + tg*4 + 1)*96 + j] = a1;
    g_R[(size_t)(t0 + tg*4 + 2)*96 + j] = a2;
    g_R[(size_t)(t0 + tg*4 + 3)*96 + j] = a3;
}

// ---------------- kernel 6: Ro = att @ bo^T ------------------------------------------
// 16 tokens/block, 256 threads = 32 h x 8 token-groups (2 tokens each). float4 loads.
__global__ void __launch_bounds__(256) k_res32(const float* __restrict__ bo) {
    extern __shared__ float xs[];     // [16][1024]
    int t0 = blockIdx.x * 16;
    const float4* xg = (const float4*)(g_att + (size_t)t0 * Cdim);
    float4* s4 = (float4*)xs;
    for (int i = threadIdx.x; i < 4096; i += 256) s4[i] = xg[i];
    __syncthreads();
    int h  = threadIdx.x & 31;
    int tg = threadIdx.x >> 5;
    const float4* b4 = (const float4*)(bo + (size_t)h*Cdim);
    const float4* x0 = (const float4*)(xs + (tg*2    )*1024);
    const float4* x1 = (const float4*)(xs + (tg*2 + 1)*1024);
    float a0 = 0.f, a1 = 0.f;
    #pragma unroll 4
    for (int iq = 0; iq < 256; iq++) {
        float4 b = b4[iq];
        float4 v0 = x0[iq], v1 = x1[iq];
        a0 += b.x*v0.x + b.y*v0.y + b.z*v0.z + b.w*v0.w;
        a1 += b.x*v1.x + b.y*v1.y + b.z*v1.z + b.w*v1.w;
    }
    g_Ro[(size_t)(t0 + tg*2    )*32 + h] = a0;
    g_Ro[(size_t)(t0 + tg*2 + 1)*32 + h] = a1;
}

// ---------------- expand resonance body ----------------------------------------------
// which 0: Q fp16 (pre-scaled, d-pair-permuted). which 1: K fp16 (d-pair-permuted).
// which 2: V fp16 transposed [bh][d][L], L-pair-permuted. which 3: final fp32 out.
__device__ __forceinline__ void proj_body(int which, float* __restrict__ dout) {
    __shared__ float Rs[8][32];
    int t0 = blockIdx.x * 8;
    int tid = threadIdx.x;
    const float* Rsrc; int rstride, roff; const float* w;
    if (which < 3) { Rsrc = g_R;  rstride = 96; roff = which*32; w = g_w[which]; }
    else           { Rsrc = g_Ro; rstride = 32; roff = 0;        w = g_w[3];     }

    {
        int t = tid >> 5, h = tid & 31;
        Rs[t][h] = Rsrc[(size_t)(t0 + t)*rstride + roff + h];
    }
    __syncthreads();

    int c0 = tid * 4;
    float acc[8][4];
    #pragma unroll
    for (int t = 0; t < 8; t++)
        #pragma unroll
        for (int j = 0; j < 4; j++) acc[t][j] = 0.f;

    #pragma unroll
    for (int h = 0; h < 32; h++) {
        float4 w4 = *(const float4*)&w[h*Cdim + c0];
        #pragma unroll
        for (int t = 0; t < 8; t++) {
            float r = Rs[t][h];
            acc[t][0] += r * w4.x;
            acc[t][1] += r * w4.y;
            acc[t][2] += r * w4.z;
            acc[t][3] += r * w4.w;
        }
    }

    if (which == 0 || which == 1) {
        __half* out = (which == 0) ? g_q : g_k;
        float s = (which == 0) ? QSCALE : 1.0f;
        int p0 = (c0 >> 1) & 7;
        int p1 = p0 + 1;
        int s0 = (p0 < 4) ? 2*p0 : 2*p0 - 7;
        int s1 = (p1 < 4) ? 2*p1 : 2*p1 - 7;
        int base = c0 & ~15;
        #pragma unroll
        for (int t = 0; t < 8; t++) {
            __half* op = out + (size_t)(t0 + t)*Cdim;
            *(unsigned*)(op + base + 2*s0) = h2pk(acc[t][0]*s, acc[t][1]*s);
            *(unsigned*)(op + base + 2*s1) = h2pk(acc[t][2]*s, acc[t][3]*s);
        }
    } else if (which == 2) {
        int bb = t0 >> 11, l0 = t0 & 2047, hh = c0 >> 6, d0 = c0 & 63;
        __half* vt = g_v + (size_t)(bb*NH + hh) * HD * Ls;
        int lbase = l0 & ~15;
        #pragma unroll
        for (int tt = 0; tt < 8; tt += 2) {
            int pg = ((l0 + tt) >> 1) & 7;
            int slot = (pg < 4) ? 2*pg : 2*pg - 7;
            int lp = lbase + 2*slot;
            #pragma unroll
            for (int j = 0; j < 4; j++)
                *(unsigned*)(vt + (size_t)(d0 + j)*Ls + lp) =
                    h2pk(acc[tt][j], acc[tt+1][j]);
        }
    } else {
        #pragma unroll
        for (int t = 0; t < 8; t++)
            *(float4*)(dout + (size_t)(t0 + t)*Cdim + c0) =
                make_float4(acc[t][0], acc[t][1], acc[t][2], acc[t][3]);
    }
}

__global__ void __launch_bounds__(256) k_proj3()  { proj_body((int)blockIdx.y, nullptr); }
__global__ void __launch_bounds__(256) k_projo(float* __restrict__ dout) { proj_body(3, dout); }

// ---------------- kernel 5: flash attention, fp16 mma, max-free softmax -------------
// Scores bounded (|S| << 1): softmax shift is a no-op, so no max tracking, no O
// rescale, no in-loop reductions. Row-sum l accumulated lane-locally; one shuffle
// reduce in the epilogue.
#define KVU 2560
#define ATTN_SMEM (4*KVU*4)   // 40960 B
__global__ void __launch_bounds__(256, 2) k_attn() {
    extern __shared__ float smem[];

    int qt = blockIdx.x, bh = blockIdx.y;
    int b = bh >> 4, h = bh & 15;
    const __half* __restrict__ Qg = g_q + (size_t)(b*Ls + qt*128)*Cdim + h*HD;
    const __half* __restrict__ Kg = g_k + (size_t)b*Ls*Cdim + h*HD;
    const __half* __restrict__ Vt = g_v + (size_t)bh*HD*Ls;
    float* __restrict__ Og = g_att + (size_t)(b*Ls + qt*128)*Cdim + h*HD;

    int tid = threadIdx.x, wid = tid >> 5, lane = tid & 31;
    int g = lane >> 2, c = lane & 3;
    int wr = wid * 16;

    auto loadKV = [&](int kt, int buf) {
        float* Kb = smem + buf*KVU;
        float* Vb = smem + 2*KVU + buf*KVU;
        #pragma unroll
        for (int u = 0; u < 4; u++) {
            int i = tid + u*256;
            int m = i >> 9, j = i & 511;
            int r = j >> 3, ch = j & 7;
            const __half* src = m ? (Vt + (size_t)r*Ls + kt*64 + ch*8)
                                  : (Kg + (size_t)(kt*64 + r)*Cdim + ch*8);
            cp16((m ? Vb : Kb) + r*40 + ch*4, src);
        }
        asm volatile("cp.async.commit_group;");
    };

    loadKV(0, 0);

    // Q A-fragments straight from permuted gmem
    unsigned qf[4][4];
    #pragma unroll
    for (int kg = 0; kg < 4; kg++) {
        const __half* r0 = Qg + (size_t)(wr + g)*Cdim + kg*16 + 4*c;
        uint2 lo = *(const uint2*)r0;
        uint2 hi = *(const uint2*)(r0 + 8*Cdim);
        qf[kg][0] = lo.x; qf[kg][1] = hi.x; qf[kg][2] = lo.y; qf[kg][3] = hi.y;
    }

    float l0 = 0.f, l1 = 0.f;
    float O[8][4];
    #pragma unroll
    for (int nt = 0; nt < 8; nt++)
        #pragma unroll
        for (int j = 0; j < 4; j++) O[nt][j] = 0.f;

    for (int kt = 0; kt < 32; kt++) {
        __syncthreads();
        if (kt + 1 < 32) {
            loadKV(kt + 1, (kt + 1) & 1);
            asm volatile("cp.async.wait_group 1;");
        } else {
            asm volatile("cp.async.wait_group 0;");
        }
        __syncthreads();

        const float* Ks = smem + (kt & 1)*KVU;
        const float* Vs = smem + 2*KVU + (kt & 1)*KVU;

        // ---- S = Q . K^T (log2-domain; 32 MMAs) ----
        float S[8][4];
        #pragma unroll
        for (int nt = 0; nt < 8; nt++)
            #pragma unroll
            for (int j = 0; j < 4; j++) S[nt][j] = 0.f;

        #pragma unroll
        for (int kg = 0; kg < 4; kg++) {
            #pragma unroll
            for (int nt = 0; nt < 8; nt++) {
                uint2 bb = *(const uint2*)&Ks[(nt*8 + g)*40 + kg*8 + 2*c];
                mma_f16(S[nt], qf[kg], bb.x, bb.y);
            }
        }

        // ---- p = exp2(S); accumulate row-sum lane-locally; pack to fp16 ----
        unsigned pf[4][4];
        #pragma unroll
        for (int nt = 0; nt < 8; nt++) {
            S[nt][0] = ex2f(S[nt][0]); S[nt][1] = ex2f(S[nt][1]);
            S[nt][2] = ex2f(S[nt][2]); S[nt][3] = ex2f(S[nt][3]);
            l0 += S[nt][0] + S[nt][1];
            l1 += S[nt][2] + S[nt][3];
        }
        #pragma unroll
        for (int kg = 0; kg < 4; kg++) {
            pf[kg][0] = h2pk(S[2*kg  ][0], S[2*kg  ][1]);
            pf[kg][1] = h2pk(S[2*kg  ][2], S[2*kg  ][3]);
            pf[kg][2] = h2pk(S[2*kg+1][0], S[2*kg+1][1]);
            pf[kg][3] = h2pk(S[2*kg+1][2], S[2*kg+1][3]);
        }

        // ---- O += P . V (32 MMAs) ----
        #pragma unroll
        for (int kg = 0; kg < 4; kg++) {
            #pragma unroll
            for (int nt = 0; nt < 8; nt++) {
                uint2 bb = *(const uint2*)&Vs[(nt*8 + g)*40 + kg*8 + 2*c];
                mma_f16(O[nt], pf[kg], bb.x, bb.y);
            }
        }
    }

    // ---- epilogue: one-shot row-sum reduce across the lane quad, then store ----
    l0 += __shfl_xor_sync(0xffffffffu, l0, 1);
    l0 += __shfl_xor_sync(0xffffffffu, l0, 2);
    l1 += __shfl_xor_sync(0xffffffffu, l1, 1);
    l1 += __shfl_xor_sync(0xffffffffu, l1, 2);
    float i0 = 1.f / l0, i1 = 1.f / l1;
    #pragma unroll
    for (int nt = 0; nt < 8; nt++) {
        float2 o0 = make_float2(O[nt][0]*i0, O[nt][1]*i0);
        float2 o1 = make_float2(O[nt][2]*i1, O[nt][3]*i1);
        *(float2*)(Og + (size_t)(wr + g    )*Cdim + nt*8 + 2*c) = o0;
        *(float2*)(Og + (size_t)(wr + g + 8)*Cdim + nt*8 + 2*c) = o1;
    }
}

// ---------------- launch -------------------------------------------------------------
extern "C" void kernel_launch(void* const* d_in, const int* in_sizes, int n_in,
                              void* d_out, int out_size) {
    const float* x  = (const float*)d_in[0];
    const float* bq = (const float*)d_in[1];
    const float* pq = (const float*)d_in[2];
    const float* aq = (const float*)d_in[3];
    const float* bk = (const float*)d_in[4];
    const float* pk = (const float*)d_in[5];
    const float* ak = (const float*)d_in[6];
    const float* bv = (const float*)d_in[7];
    const float* pv = (const float*)d_in[8];
    const float* av = (const float*)d_in[9];
    const float* bo = (const float*)d_in[10];
    const float* po = (const float*)d_in[11];
    const float* ao = (const float*)d_in[12];
    float* out = (float*)d_out;

    static bool attr_set = false;
    if (!attr_set) {
        cudaFuncSetAttribute(k_attn,  cudaFuncAttributeMaxDynamicSharedMemorySize, ATTN_SMEM);
        cudaFuncSetAttribute(k_res96, cudaFuncAttributeMaxDynamicSharedMemorySize, 65536);
        cudaFuncSetAttribute(k_res32, cudaFuncAttributeMaxDynamicSharedMemorySize, 65536);
        attr_set = true;
    }

    k_w    <<<128, 256>>>(pq, aq, pk, ak, pv, av, po, ao);
    k_res96<<<TOK/16, 384, 65536>>>(x, bq, bk, bv);
    k_proj3<<<dim3(TOK/8, 3), 256>>>();
    k_attn <<<dim3(Ls/128, Bsz*NH), 256, ATTN_SMEM>>>();
    k_res32<<<TOK/16, 256, 65536>>>(bo);
    k_projo<<<TOK/8, 256>>>(out);
}

// round 17
// speedup vs baseline: 1.3311x; 1.3311x over previous
#include <cuda_runtime.h>
#include <cuda_fp16.h>
#include <math.h>

#define Bsz   2
#define Ls    2048
#define Cdim  1024
#define NH    16
#define HD    64
#define HARM  32
#define TOK   (Bsz*Ls)   // 4096

// ---------------- device scratch ----------------------------------------------------
__device__ float  g_w[4][HARM*Cdim];     // w transposed: [h][o]
__device__ float  g_Bt[Cdim*96];         // stacked qkv basis, transposed (coalesced reads)
__device__ float  g_BoT[Cdim*HARM];      // basis_o transposed
__device__ float  g_R[TOK*96];           // qkv resonances
__device__ __half g_q[TOK*Cdim];         // Q fp16, pre-scaled by scale*log2e, d-pair-permuted
__device__ __half g_k[TOK*Cdim];         // K fp16, d-pair-permuted
__device__ __half g_v[Bsz*NH*HD*Ls];     // V fp16, transposed [bh][d][L], L-pair-permuted
__device__ float  g_att[TOK*Cdim];       // attention output [B,L,C] fp32
__device__ float  g_Ro[TOK*HARM];        // output-projection resonance

#define QSCALE (0.125f * 1.44269504088896340736f)   // headdim^-0.5 * log2(e)

__device__ __forceinline__ float ex2f(float x) {
    float r; asm("ex2.approx.f32 %0, %1;" : "=f"(r) : "f"(x)); return r;
}
__device__ __forceinline__ unsigned h2pk(float lo, float hi) {
    unsigned r; asm("cvt.rn.f16x2.f32 %0, %1, %2;" : "=r"(r) : "f"(hi), "f"(lo)); return r;
}
__device__ __forceinline__ void mma_f16(float d[4], const unsigned a[4],
                                        unsigned b0, unsigned b1) {
    asm("mma.sync.aligned.m16n8k16.row.col.f32.f16.f16.f32 "
        "{%0,%1,%2,%3}, {%4,%5,%6,%7}, {%8,%9}, {%0,%1,%2,%3};"
        : "+f"(d[0]), "+f"(d[1]), "+f"(d[2]), "+f"(d[3])
        : "r"(a[0]), "r"(a[1]), "r"(a[2]), "r"(a[3]), "r"(b0), "r"(b1));
}
__device__ __forceinline__ void cp16(float* dst, const void* src) {
    unsigned d = (unsigned)__cvta_generic_to_shared(dst);
    asm volatile("cp.async.cg.shared.global [%0], [%1], 16;" :: "r"(d), "l"(src));
}

// ---------------- kernel 1: w = amp * cos(phase), stored transposed [h][o] ----------
__global__ void k_w(const float* __restrict__ pq, const float* __restrict__ aq,
                    const float* __restrict__ pk, const float* __restrict__ ak,
                    const float* __restrict__ pv, const float* __restrict__ av,
                    const float* __restrict__ po, const float* __restrict__ ao) {
    int i = blockIdx.x * blockDim.x + threadIdx.x;
    int o = i >> 5, h = i & 31;
    int j = h * Cdim + o;
    g_w[0][j] = aq[i] * cosf(pq[i]);
    g_w[1][j] = ak[i] * cosf(pk[i]);
    g_w[2][j] = av[i] * cosf(pv[i]);
    g_w[3][j] = ao[i] * cosf(po[i]);
}

// ---------------- kernel 2: transpose + stack bases (for coalesced GEMM reads) ------
__global__ void k_tr(const float* __restrict__ bq, const float* __restrict__ bk,
                     const float* __restrict__ bv, const float* __restrict__ bo) {
    int i = blockIdx.x * blockDim.x + threadIdx.x;
    int h = i >> 10, d = i & 1023;
    g_Bt[d*96 + h]      = bq[i];
    g_Bt[d*96 + 32 + h] = bk[i];
    g_Bt[d*96 + 64 + h] = bv[i];
    g_BoT[d*32 + h]     = bo[i];
}

// ---------------- kernel 3: R = x @ Bt  ([4096,1024] x [1024,96]) -------------------
// 16 tokens/block, 384 threads = 96 j-cols x 4 token-groups. Coalesced g_Bt reads.
__global__ void __launch_bounds__(384) k_res96(const float* __restrict__ x) {
    extern __shared__ float xs[];     // [16][1024]
    int t0 = blockIdx.x * 16;
    const float4* xg = (const float4*)(x + (size_t)t0 * Cdim);
    float4* s4 = (float4*)xs;
    for (int i = threadIdx.x; i < 4096; i += 384) s4[i] = xg[i];
    __syncthreads();
    int j  = threadIdx.x % 96;
    int tg = threadIdx.x / 96;
    const float* x0 = xs + (tg*4 + 0)*1024;
    const float* x1 = xs + (tg*4 + 1)*1024;
    const float* x2 = xs + (tg*4 + 2)*1024;
    const float* x3 = xs + (tg*4 + 3)*1024;
    float a0 = 0.f, a1 = 0.f, a2 = 0.f, a3 = 0.f;
    #pragma unroll 8
    for (int i = 0; i < 1024; i++) {
        float b = g_Bt[i*96 + j];
        a0 += x0[i] * b; a1 += x1[i] * b; a2 += x2[i] * b; a3 += x3[i] * b;
    }
    g_R[(size_t)(t0 + tg*4    )*96 + j] = a0;
    g_R[(size_t)(t0 + tg*4 + 1)*96 + j] = a1;
    g_R[(size_t)(t0 + tg*4 + 2)*96 + j] = a2;
    g_R[(size_t)(t0 + tg*4 + 3)*96 + j] = a3;
}

// ---------------- kernel 6: Ro = att @ BoT ------------------------------------------
__global__ void __launch_bounds__(256) k_res32() {
    extern __shared__ float xs[];     // [16][1024]
    int t0 = blockIdx.x * 16;
    const float4* xg = (const float4*)(g_att + (size_t)t0 * Cdim);
    float4* s4 = (float4*)xs;
    for (int i = threadIdx.x; i < 4096; i += 256) s4[i] = xg[i];
    __syncthreads();
    int h  = threadIdx.x & 31;
    int tg = threadIdx.x >> 5;
    const float* x0 = xs + (tg*2    )*1024;
    const float* x1 = xs + (tg*2 + 1)*1024;
    float a0 = 0.f, a1 = 0.f;
    #pragma unroll 8
    for (int i = 0; i < 1024; i++) {
        float b = g_BoT[i*32 + h];
        a0 += x0[i] * b; a1 += x1[i] * b;
    }
    g_Ro[(size_t)(t0 + tg*2    )*32 + h] = a0;
    g_Ro[(size_t)(t0 + tg*2 + 1)*32 + h] = a1;
}

// ---------------- expand resonance body ----------------------------------------------
// which 0: Q fp16 (pre-scaled, d-pair-permuted). which 1: K fp16 (d-pair-permuted).
// which 2: V fp16 transposed [bh][d][L], L-pair-permuted. which 3: final fp32 out.
__device__ __forceinline__ void proj_body(int which, float* __restrict__ dout) {
    __shared__ float Rs[8][32];
    int t0 = blockIdx.x * 8;
    int tid = threadIdx.x;
    const float* Rsrc; int rstride, roff; const float* w;
    if (which < 3) { Rsrc = g_R;  rstride = 96; roff = which*32; w = g_w[which]; }
    else           { Rsrc = g_Ro; rstride = 32; roff = 0;        w = g_w[3];     }

    {
        int t = tid >> 5, h = tid & 31;
        Rs[t][h] = Rsrc[(size_t)(t0 + t)*rstride + roff + h];
    }
    __syncthreads();

    int c0 = tid * 4;
    float acc[8][4];
    #pragma unroll
    for (int t = 0; t < 8; t++)
        #pragma unroll
        for (int j = 0; j < 4; j++) acc[t][j] = 0.f;

    #pragma unroll
    for (int h = 0; h < 32; h++) {
        float4 w4 = *(const float4*)&w[h*Cdim + c0];
        #pragma unroll
        for (int t = 0; t < 8; t++) {
            float r = Rs[t][h];
            acc[t][0] += r * w4.x;
            acc[t][1] += r * w4.y;
            acc[t][2] += r * w4.z;
            acc[t][3] += r * w4.w;
        }
    }

    if (which == 0 || which == 1) {
        __half* out = (which == 0) ? g_q : g_k;
        float s = (which == 0) ? QSCALE : 1.0f;
        int p0 = (c0 >> 1) & 7;
        int p1 = p0 + 1;
        int s0 = (p0 < 4) ? 2*p0 : 2*p0 - 7;
        int s1 = (p1 < 4) ? 2*p1 : 2*p1 - 7;
        int base = c0 & ~15;
        #pragma unroll
        for (int t = 0; t < 8; t++) {
            __half* op = out + (size_t)(t0 + t)*Cdim;
            *(unsigned*)(op + base + 2*s0) = h2pk(acc[t][0]*s, acc[t][1]*s);
            *(unsigned*)(op + base + 2*s1) = h2pk(acc[t][2]*s, acc[t][3]*s);
        }
    } else if (which == 2) {
        int bb = t0 >> 11, l0 = t0 & 2047, hh = c0 >> 6, d0 = c0 & 63;
        __half* vt = g_v + (size_t)(bb*NH + hh) * HD * Ls;
        int lbase = l0 & ~15;
        #pragma unroll
        for (int tt = 0; tt < 8; tt += 2) {
            int pg = ((l0 + tt) >> 1) & 7;
            int slot = (pg < 4) ? 2*pg : 2*pg - 7;
            int lp = lbase + 2*slot;
            #pragma unroll
            for (int j = 0; j < 4; j++)
                *(unsigned*)(vt + (size_t)(d0 + j)*Ls + lp) =
                    h2pk(acc[tt][j], acc[tt+1][j]);
        }
    } else {
        #pragma unroll
        for (int t = 0; t < 8; t++)
            *(float4*)(dout + (size_t)(t0 + t)*Cdim + c0) =
                make_float4(acc[t][0], acc[t][1], acc[t][2], acc[t][3]);
    }
}

__global__ void __launch_bounds__(256) k_proj3()  { proj_body((int)blockIdx.y, nullptr); }
__global__ void __launch_bounds__(256) k_projo(float* __restrict__ dout) { proj_body(3, dout); }

// ---------------- kernel 5: flash attention, fp16 mma, max-free softmax -------------
#define KVU 2560
#define ATTN_SMEM (4*KVU*4)   // 40960 B
__global__ void __launch_bounds__(256, 2) k_attn() {
    extern __shared__ float smem[];

    int qt = blockIdx.x, bh = blockIdx.y;
    int b = bh >> 4, h = bh & 15;
    const __half* __restrict__ Qg = g_q + (size_t)(b*Ls + qt*128)*Cdim + h*HD;
    const __half* __restrict__ Kg = g_k + (size_t)b*Ls*Cdim + h*HD;
    const __half* __restrict__ Vt = g_v + (size_t)bh*HD*Ls;
    float* __restrict__ Og = g_att + (size_t)(b*Ls + qt*128)*Cdim + h*HD;

    int tid = threadIdx.x, wid = tid >> 5, lane = tid & 31;
    int g = lane >> 2, c = lane & 3;
    int wr = wid * 16;

    auto loadKV = [&](int kt, int buf) {
        float* Kb = smem + buf*KVU;
        float* Vb = smem + 2*KVU + buf*KVU;
        #pragma unroll
        for (int u = 0; u < 4; u++) {
            int i = tid + u*256;
            int m = i >> 9, j = i & 511;
            int r = j >> 3, ch = j & 7;
            const __half* src = m ? (Vt + (size_t)r*Ls + kt*64 + ch*8)
                                  : (Kg + (size_t)(kt*64 + r)*Cdim + ch*8);
            cp16((m ? Vb : Kb) + r*40 + ch*4, src);
        }
        asm volatile("cp.async.commit_group;");
    };

    loadKV(0, 0);

    // Q A-fragments straight from permuted gmem
    unsigned qf[4][4];
    #pragma unroll
    for (int kg = 0; kg < 4; kg++) {
        const __half* r0 = Qg + (size_t)(wr + g)*Cdim + kg*16 + 4*c;
        uint2 lo = *(const uint2*)r0;
        uint2 hi = *(const uint2*)(r0 + 8*Cdim);
        qf[kg][0] = lo.x; qf[kg][1] = hi.x; qf[kg][2] = lo.y; qf[kg][3] = hi.y;
    }

    float l0 = 0.f, l1 = 0.f;
    float O[8][4];
    #pragma unroll
    for (int nt = 0; nt < 8; nt++)
        #pragma unroll
        for (int j = 0; j < 4; j++) O[nt][j] = 0.f;

    for (int kt = 0; kt < 32; kt++) {
        __syncthreads();
        if (kt + 1 < 32) {
            loadKV(kt + 1, (kt + 1) & 1);
            asm volatile("cp.async.wait_group 1;");
        } else {
            asm volatile("cp.async.wait_group 0;");
        }
        __syncthreads();

        const float* Ks = smem + (kt & 1)*KVU;
        const float* Vs = smem + 2*KVU + (kt & 1)*KVU;

        // ---- S = Q . K^T (log2-domain; 32 MMAs) ----
        float S[8][4];
        #pragma unroll
        for (int nt = 0; nt < 8; nt++)
            #pragma unroll
            for (int j = 0; j < 4; j++) S[nt][j] = 0.f;

        #pragma unroll
        for (int kg = 0; kg < 4; kg++) {
            #pragma unroll
            for (int nt = 0; nt < 8; nt++) {
                uint2 bb = *(const uint2*)&Ks[(nt*8 + g)*40 + kg*8 + 2*c];
                mma_f16(S[nt], qf[kg], bb.x, bb.y);
            }
        }

        // ---- p = exp2(S); lane-local row-sum; pack to fp16 A-frags ----
        unsigned pf[4][4];
        #pragma unroll
        for (int nt = 0; nt < 8; nt++) {
            S[nt][0] = ex2f(S[nt][0]); S[nt][1] = ex2f(S[nt][1]);
            S[nt][2] = ex2f(S[nt][2]); S[nt][3] = ex2f(S[nt][3]);
            l0 += S[nt][0] + S[nt][1];
            l1 += S[nt][2] + S[nt][3];
        }
        #pragma unroll
        for (int kg = 0; kg < 4; kg++) {
            pf[kg][0] = h2pk(S[2*kg  ][0], S[2*kg  ][1]);
            pf[kg][1] = h2pk(S[2*kg  ][2], S[2*kg  ][3]);
            pf[kg][2] = h2pk(S[2*kg+1][0], S[2*kg+1][1]);
            pf[kg][3] = h2pk(S[2*kg+1][2], S[2*kg+1][3]);
        }

        // ---- O += P . V (32 MMAs) ----
        #pragma unroll
        for (int kg = 0; kg < 4; kg++) {
            #pragma unroll
            for (int nt = 0; nt < 8; nt++) {
                uint2 bb = *(const uint2*)&Vs[(nt*8 + g)*40 + kg*8 + 2*c];
                mma_f16(O[nt], pf[kg], bb.x, bb.y);
            }
        }
    }

    // ---- epilogue ----
    l0 += __shfl_xor_sync(0xffffffffu, l0, 1);
    l0 += __shfl_xor_sync(0xffffffffu, l0, 2);
    l1 += __shfl_xor_sync(0xffffffffu, l1, 1);
    l1 += __shfl_xor_sync(0xffffffffu, l1, 2);
    float i0 = 1.f / l0, i1 = 1.f / l1;
    #pragma unroll
    for (int nt = 0; nt < 8; nt++) {
        float2 o0 = make_float2(O[nt][0]*i0, O[nt][1]*i0);
        float2 o1 = make_float2(O[nt][2]*i1, O[nt][3]*i1);
        *(float2*)(Og + (size_t)(wr + g    )*Cdim + nt*8 + 2*c) = o0;
        *(float2*)(Og + (size_t)(wr + g + 8)*Cdim + nt*8 + 2*c) = o1;
    }
}

// ---------------- launch -------------------------------------------------------------
extern "C" void kernel_launch(void* const* d_in, const int* in_sizes, int n_in,
                              void* d_out, int out_size) {
    const float* x  = (const float*)d_in[0];
    const float* bq = (const float*)d_in[1];
    const float* pq = (const float*)d_in[2];
    const float* aq = (const float*)d_in[3];
    const float* bk = (const float*)d_in[4];
    const float* pk = (const float*)d_in[5];
    const float* ak = (const float*)d_in[6];
    const float* bv = (const float*)d_in[7];
    const float* pv = (const float*)d_in[8];
    const float* av = (const float*)d_in[9];
    const float* bo = (const float*)d_in[10];
    const float* po = (const float*)d_in[11];
    const float* ao = (const float*)d_in[12];
    float* out = (float*)d_out;

    static bool attr_set = false;
    if (!attr_set) {
        cudaFuncSetAttribute(k_attn,  cudaFuncAttributeMaxDynamicSharedMemorySize, ATTN_SMEM);
        cudaFuncSetAttribute(k_res96, cudaFuncAttributeMaxDynamicSharedMemorySize, 65536);
        cudaFuncSetAttribute(k_res32, cudaFuncAttributeMaxDynamicSharedMemorySize, 65536);
        attr_set = true;
    }

    k_w    <<<128, 256>>>(pq, aq, pk, ak, pv, av, po, ao);
    k_tr   <<<128, 256>>>(bq, bk, bv, bo);
    k_res96<<<TOK/16, 384, 65536>>>(x);
    k_proj3<<<dim3(TOK/8, 3), 256>>>();
    k_attn <<<dim3(Ls/128, Bsz*NH), 256, ATTN_SMEM>>>();
    k_res32<<<TOK/16, 256, 65536>>>();
    k_projo<<<TOK/8, 256>>>(out);
}